// round 12
// baseline (speedup 1.0000x reference)
#include <cuda_runtime.h>
#include <math.h>
#include <stdint.h>

// MemoryUnit, Round 11: 2-CTA cluster per batch element, 512 threads/CTA.
// vs R10: eg/wc GEMM split A/B by i-range (A: [0,112) at phase heads, B:
// [112,256)) with smem partial combine after B2; epilogue + gstat exchange
// moved to phase 3 (B3 sync); mean/rstd after B3. Critical-warp FFMA 4.6K->2.9K.

namespace {
constexpr int S_ = 2048;
constexpr int B_ = 64;
constexpr int D_ = 256;
constexpr int K_ = 16;
constexpr int NT = 512;
constexpr float EPSLN = 1e-5f;
constexpr float MOMC  = 0.9f;

__device__ __forceinline__ float geluf(float v) {
    return 0.5f * v * (1.0f + erff(v * 0.70710678118654752440f));
}
__device__ __forceinline__ float sigmf(float v) {
    return 1.0f / (1.0f + expf(-v));
}
__device__ __forceinline__ uint32_t smem_u32(const void* p) {
    return (uint32_t)__cvta_generic_to_shared(const_cast<void*>(p));
}
__device__ __forceinline__ uint32_t peer_addr(uint32_t la, uint32_t peer) {
    uint32_t ra;
    asm("mapa.shared::cluster.u32 %0, %1, %2;" : "=r"(ra) : "r"(la), "r"(peer));
    return ra;
}
__device__ __forceinline__ void st_peer_f32(uint32_t ra, float v) {
    asm volatile("st.shared::cluster.f32 [%0], %1;" :: "r"(ra), "f"(v) : "memory");
}
__device__ __forceinline__ void st_peer_f128(uint32_t ra, float4 v) {
    asm volatile("st.shared::cluster.v4.f32 [%0], {%1,%2,%3,%4};"
                 :: "r"(ra), "f"(v.x), "f"(v.y), "f"(v.z), "f"(v.w) : "memory");
}
__device__ __forceinline__ void cluster_sync_() {
    asm volatile("barrier.cluster.arrive.aligned;\n\t"
                 "barrier.cluster.wait.aligned;" ::: "memory");
}
__device__ __forceinline__ void barA() { asm volatile("bar.sync 1, 256;" ::: "memory"); }
__device__ __forceinline__ void barB() { asm volatile("bar.sync 2, 256;" ::: "memory"); }
} // namespace

__global__ __launch_bounds__(NT, 1) __cluster_dims__(2, 1, 1)
void memunit_kernel(
    const float* __restrict__ x,     const float* __restrict__ slot_init,
    const float* __restrict__ Wq,    const float* __restrict__ bq,
    const float* __restrict__ Wk,    const float* __restrict__ bk,
    const float* __restrict__ Wv,    const float* __restrict__ bv,
    const float* __restrict__ wg1W,  const float* __restrict__ wg1b,
    const float* __restrict__ wg2W,  const float* __restrict__ wg2b,
    const float* __restrict__ egW,   const float* __restrict__ egb,
    const float* __restrict__ wcW,   const float* __restrict__ wcb,
    const float* __restrict__ wclng, const float* __restrict__ wclnb,
    const float* __restrict__ fuW,   const float* __restrict__ fub,
    const float* __restrict__ fulng, const float* __restrict__ fulnb,
    const float* __restrict__ ong,   const float* __restrict__ onb,
    float* __restrict__ out)
{
    __shared__ float sM[D_][K_];       // full M, feature-major, peer-mirrored
    __shared__ float scat[2 * D_];     // [x_t | r]
    __shared__ float sQ[D_];           // full q (with bias)
    __shared__ float sQh[128], sRh[128]; // helper-half partials for q and r
    __shared__ float sKv[128];         // Wk @ q for my CTA's i-rows
    __shared__ float sMbar[D_];        // attn-weighted slot average
    __shared__ float sAP[256][17];     // A's GEMM partials: 16 slots + aux
    __shared__ float sG[128][K_];      // gelu(write pre-act), local-o rows
    __shared__ float sE[128][K_];      // sigmoid(erase pre-act)
    __shared__ float sLP[4][K_];       // logit warp partials
    __shared__ float sGP[4][2 * K_];   // wc-warp gstat partials
    __shared__ float sGloc[2 * K_], eG[2 * K_];
    __shared__ float sLoc[K_], eL[K_];
    __shared__ float sFBf[128], sFBg[128]; // B's fu-hi / wg1-hi partials per o
    __shared__ float sBRf[4][2];       // fu-LN warp partials (A warps 0-3)
    __shared__ float sBRg[4];          // wg2 warp partials (A warps 4-7)
    __shared__ float sUW[4][2];        // out-LN warp partials
    __shared__ float sF[3], eF[3], sU[2], eU[2];
    __shared__ float sAttn[K_], sEvict[K_], sPers[K_], sMean[K_], sRstd[K_];
    __shared__ float sNov;

    const int tid  = threadIdx.x;
    const int lane = tid & 31;
    const int wid  = tid >> 5;
    const bool isA = tid < 256;
    const int gt   = tid & 255;
    const int o    = gt & 127;         // local output feature
    const int hb   = gt >> 7;          // matrix select (0=eg, 1=wc); A: also q/r half
    uint32_t rank;
    asm("mov.u32 %0, %%cluster_ctarank;" : "=r"(rank));
    const uint32_t peer = rank ^ 1u;
    const int b  = blockIdx.x >> 1;
    const int og = (int)rank * 128 + o;

    if (tid < D_) {
        #pragma unroll
        for (int j = 0; j < K_; ++j) sM[tid][j] = slot_init[j * D_ + tid];
    }
    if (tid < K_) sPers[tid] = 0.f;

    const float wg2b0 = wg2b[0];
    float cA0 = 0.f, cA1 = 0.f, cA2 = 0.f, cA3 = 0.f, cA4 = 0.f;
    float ongo = 0.f, onbo = 0.f;
    if (isA) {
        if (hb == 0) {
            cA0 = bq[og]; cA1 = bv[og]; cA2 = fub[og];
            cA3 = fulng[og]; cA4 = fulnb[og];
            ongo = ong[og]; onbo = onb[og];
        } else {
            cA2 = wg1b[og]; cA3 = wg2W[og];
        }
    }
    const float cbM = hb ? wcb[og] : egb[og];   // B epilogue bias (A unused)
    const int  urow = gt >> 1;                  // B M-update row
    const int  grow = (int)rank * 128 + urow;
    float cgU = 0.f, cbU = 0.f;
    if (!isA) { cgU = wclng[grow]; cbU = wclnb[grow]; }
    const float* Wm = hb ? wcW : egW;           // GEMM matrix (both groups)
    const float* Wf = hb ? wg1W : fuW;          // fu/wg1 matrix per role
    __syncthreads();

    for (int t = 0; t < S_; ++t) {
        if (tid < D_) scat[tid] = x[((size_t)t * B_ + b) * D_ + tid];
        __syncthreads();

        // GEMM accumulators — shared variable set for A and B
        float acc[K_];
        float aux = 0.f;
        #pragma unroll
        for (int j = 0; j < K_; ++j) acc[j] = 0.f;

        // eg/wc GEMM chunk: 16 slots + x-part, 1 scalar weight per (i,part)
        auto chunk = [&](int c0, int c1) {
            for (int c = c0; c < c1; c += 4) {
                float wa[4], ws[4];
                #pragma unroll
                for (int u = 0; u < 4; ++u) {
                    wa[u] = Wm[(c + u) * D_ + og];          // x-part row
                    ws[u] = Wm[(D_ + c + u) * D_ + og];     // slot-part row
                }
                #pragma unroll
                for (int u = 0; u < 4; ++u) {
                    const int i = c + u;
                    aux = fmaf(scat[i], wa[u], aux);
                    const float4* mr = reinterpret_cast<const float4*>(sM[i]);
                    const float4 m0 = mr[0], m1 = mr[1], m2 = mr[2], m3 = mr[3];
                    const float mv[K_] = {m0.x,m0.y,m0.z,m0.w, m1.x,m1.y,m1.z,m1.w,
                                          m2.x,m2.y,m2.z,m2.w, m3.x,m3.y,m3.z,m3.w};
                    #pragma unroll
                    for (int j = 0; j < K_; ++j)
                        acc[j] = fmaf(mv[j], ws[u], acc[j]);
                }
            }
        };

        // ================= PHASE 0 =================
        if (isA) {
            chunk(0, 40);
            // q = x @ Wq + bq, split over i-halves (hb)
            float qp = 0.f;
            const int i0 = hb << 7;
            for (int c = 0; c < 128; c += 8) {
                float w[8];
                #pragma unroll
                for (int u = 0; u < 8; ++u) w[u] = Wq[(i0 + c + u) * D_ + og];
                #pragma unroll
                for (int u = 0; u < 8; ++u) qp = fmaf(scat[i0 + c + u], w[u], qp);
            }
            if (hb) sQh[o] = qp;
            barA();
            if (!hb) {
                const float q = qp + sQh[o] + cA0;
                sQ[og] = q;
                st_peer_f32(peer_addr(smem_u32(&sQ[og]), peer), q);
            }
        } else chunk(112, 160);
        cluster_sync_();   // B0: full q visible in both CTAs

        // ================= PHASE 1 =================
        if (isA) {
            chunk(40, 76);
            // Kvec: 8 warps, warp-per-row
            const float4 q4lo = reinterpret_cast<const float4*>(sQ)[lane];
            const float4 q4hi = reinterpret_cast<const float4*>(sQ)[lane + 32];
            for (int r = wid; r < 128; r += 8) {
                const float* wr = Wk + (size_t)((int)rank * 128 + r) * D_;
                const float4 wlo = reinterpret_cast<const float4*>(wr)[lane];
                const float4 whi = reinterpret_cast<const float4*>(wr)[lane + 32];
                float a = wlo.x * q4lo.x;
                a = fmaf(wlo.y, q4lo.y, a);
                a = fmaf(wlo.z, q4lo.z, a);
                a = fmaf(wlo.w, q4lo.w, a);
                a = fmaf(whi.x, q4hi.x, a);
                a = fmaf(whi.y, q4hi.y, a);
                a = fmaf(whi.z, q4hi.z, a);
                a = fmaf(whi.w, q4hi.w, a);
                #pragma unroll
                for (int off = 16; off; off >>= 1)
                    a += __shfl_xor_sync(0xffffffffu, a, off);
                if (lane == 0) sKv[r] = a;
            }
            barA();
            if (gt < 128) {  // logit partials: thread = i-row (warps 0-3)
                const int gi = (int)rank * 128 + gt;
                const float kv = sKv[gt];
                const float4* mr = reinterpret_cast<const float4*>(sM[gi]);
                const float4 m0 = mr[0], m1 = mr[1], m2 = mr[2], m3 = mr[3];
                const float mv[K_] = {m0.x,m0.y,m0.z,m0.w, m1.x,m1.y,m1.z,m1.w,
                                      m2.x,m2.y,m2.z,m2.w, m3.x,m3.y,m3.z,m3.w};
                float p[K_];
                #pragma unroll
                for (int j = 0; j < K_; ++j) p[j] = mv[j] * kv;
                #pragma unroll
                for (int off = 1; off < 32; off <<= 1) {
                    #pragma unroll
                    for (int j = 0; j < K_; ++j)
                        p[j] += __shfl_xor_sync(0xffffffffu, p[j], off);
                }
                if (lane == 0) {
                    #pragma unroll
                    for (int j = 0; j < K_; ++j) sLP[wid][j] = p[j];
                }
            }
            barA();
            if (tid < K_) {
                const float s = sLP[0][tid] + sLP[1][tid] + sLP[2][tid] + sLP[3][tid];
                sLoc[tid] = s;
                st_peer_f32(peer_addr(smem_u32(&eL[tid]), peer), s);
            }
        } else chunk(160, 208);
        cluster_sync_();   // B1: logit halves exchanged

        // ================= PHASE 2 =================
        if (isA) {
            chunk(76, 112);
            if (tid < K_) {   // softmax / pers / evict
                float l = (sLoc[tid] + eL[tid]) * 0.0625f;
                float mx = l;
                #pragma unroll
                for (int off = 8; off; off >>= 1) mx = fmaxf(mx, __shfl_xor_sync(0xffffu, mx, off, 16));
                const float e = expf(l - mx);
                float s = e;
                #pragma unroll
                for (int off = 8; off; off >>= 1) s += __shfl_xor_sync(0xffffu, s, off, 16);
                const float a = e / s;
                sAttn[tid] = a;
                if (tid == 0) sNov = 1.f - 1.f / s;
                const float pr = MOMC * sPers[tid] + (1.f - MOMC) * a;
                sPers[tid] = pr;
                float el = -4.f * pr, em = el;
                #pragma unroll
                for (int off = 8; off; off >>= 1) em = fmaxf(em, __shfl_xor_sync(0xffffu, em, off, 16));
                const float ee = expf(el - em);
                float es = ee;
                #pragma unroll
                for (int off = 8; off; off >>= 1) es += __shfl_xor_sync(0xffffu, es, off, 16);
                sEvict[tid] = ee / es;
            }
            barA();
            {   // m-bar: one feature per A thread
                const int f = gt;
                const float4* mr = reinterpret_cast<const float4*>(sM[f]);
                const float4 m0 = mr[0], m1 = mr[1], m2 = mr[2], m3 = mr[3];
                const float mv[K_] = {m0.x,m0.y,m0.z,m0.w, m1.x,m1.y,m1.z,m1.w,
                                      m2.x,m2.y,m2.z,m2.w, m3.x,m3.y,m3.z,m3.w};
                float a = 0.f;
                #pragma unroll
                for (int j = 0; j < K_; ++j) a = fmaf(sAttn[j], mv[j], a);
                sMbar[f] = a;
            }
            barA();
            // r = m-bar @ Wv + bv, split over i-halves (hb)
            float rp = 0.f;
            const int i0 = hb << 7;
            for (int c = 0; c < 128; c += 8) {
                float w[8];
                #pragma unroll
                for (int u = 0; u < 8; ++u) w[u] = Wv[(i0 + c + u) * D_ + og];
                #pragma unroll
                for (int u = 0; u < 8; ++u) rp = fmaf(sMbar[i0 + c + u], w[u], rp);
            }
            if (hb) sRh[o] = rp;
            barA();
            if (!hb) {
                const float r = rp + sRh[o] + cA1;
                scat[D_ + og] = r;
                st_peer_f32(peer_addr(smem_u32(&scat[D_ + og]), peer), r);
            }
            // publish A's GEMM partials for B
            #pragma unroll
            for (int j = 0; j < K_; ++j) sAP[gt][j] = acc[j];
            sAP[gt][16] = aux;
        } else chunk(208, 256);
        cluster_sync_();   // B2: cat complete + A partials visible

        // ================= PHASE 3 =================
        // fu / wg1 quadrants: A = cat[0..255], B = cat[256..511]; matrix = hb
        float accf = 0.f;
        {
            const int base = isA ? 0 : 256;
            for (int c = 0; c < 256; c += 8) {
                float w[8];
                #pragma unroll
                for (int u = 0; u < 8; ++u) w[u] = Wf[(base + c + u) * D_ + og];
                #pragma unroll
                for (int u = 0; u < 8; ++u) accf = fmaf(scat[base + c + u], w[u], accf);
            }
        }
        if (!isA) {
            if (hb == 0) sFBf[o] = accf; else sFBg[o] = accf;
            // combine A's GEMM partials, then epilogue
            #pragma unroll
            for (int j = 0; j < K_; ++j) acc[j] += sAP[gt][j];
            aux += sAP[gt][16];
            if (hb == 0) {   // erase epilogue (warps 8-11)
                float e[K_];
                #pragma unroll
                for (int j = 0; j < K_; ++j) e[j] = sigmf(acc[j] + aux + cbM);
                float4* er = reinterpret_cast<float4*>(sE[o]);
                er[0] = make_float4(e[0],  e[1],  e[2],  e[3]);
                er[1] = make_float4(e[4],  e[5],  e[6],  e[7]);
                er[2] = make_float4(e[8],  e[9],  e[10], e[11]);
                er[3] = make_float4(e[12], e[13], e[14], e[15]);
            } else {         // write-candidate epilogue + gstats (warps 12-15)
                float g[K_], gs[K_], gq[K_];
                #pragma unroll
                for (int j = 0; j < K_; ++j) {
                    g[j]  = geluf(acc[j] + aux + cbM);
                    gs[j] = g[j];
                    gq[j] = g[j] * g[j];
                }
                #pragma unroll
                for (int off = 1; off < 32; off <<= 1) {
                    #pragma unroll
                    for (int j = 0; j < K_; ++j) {
                        gs[j] += __shfl_xor_sync(0xffffffffu, gs[j], off);
                        gq[j] += __shfl_xor_sync(0xffffffffu, gq[j], off);
                    }
                }
                if (lane == 0) {
                    #pragma unroll
                    for (int j = 0; j < K_; ++j) {
                        sGP[wid - 12][j]      = gs[j];
                        sGP[wid - 12][K_ + j] = gq[j];
                    }
                }
                float4* gr = reinterpret_cast<float4*>(sG[o]);
                gr[0] = make_float4(g[0],  g[1],  g[2],  g[3]);
                gr[1] = make_float4(g[4],  g[5],  g[6],  g[7]);
                gr[2] = make_float4(g[8],  g[9],  g[10], g[11]);
                gr[3] = make_float4(g[12], g[13], g[14], g[15]);
            }
        }
        __syncthreads();   // sFBf/sFBg + sGP visible
        float hf = 0.f;
        if (isA) {
            if (hb == 0) {
                hf = geluf(accf + sFBf[o] + cA2);
                float b0 = hf, b1 = hf * hf;
                #pragma unroll
                for (int off = 1; off < 32; off <<= 1) {
                    b0 += __shfl_xor_sync(0xffffffffu, b0, off);
                    b1 += __shfl_xor_sync(0xffffffffu, b1, off);
                }
                if (lane == 0) { sBRf[wid][0] = b0; sBRf[wid][1] = b1; }
            } else {
                const float hg = geluf(accf + sFBg[o] + cA2);
                float a2 = hg * cA3;
                #pragma unroll
                for (int off = 1; off < 32; off <<= 1)
                    a2 += __shfl_xor_sync(0xffffffffu, a2, off);
                if (lane == 0) sBRg[wid - 4] = a2;
            }
            barA();
            if (tid < 3) {
                float s;
                if (tid < 2) s = sBRf[0][tid] + sBRf[1][tid] + sBRf[2][tid] + sBRf[3][tid];
                else         s = sBRg[0] + sBRg[1] + sBRg[2] + sBRg[3];
                sF[tid] = s;
                st_peer_f32(peer_addr(smem_u32(&eF[tid]), peer), s);
            }
        } else if (gt < 2 * K_) {
            const float s = sGP[0][gt] + sGP[1][gt] + sGP[2][gt] + sGP[3][gt];
            sGloc[gt] = s;
            st_peer_f32(peer_addr(smem_u32(&eG[gt]), peer), s);
        }
        cluster_sync_();   // B3: fu-LN + wg2 + gstat partials exchanged

        // ================= PHASE 4 =================
        const float gw = sigmf(sF[2] + eF[2] + wg2b0) * sNov;
        if (tid < K_) {
            sPers[tid] += sEvict[tid] * gw * 0.1f;
            const float gsum = sGloc[tid] + eG[tid];
            const float gsq  = sGloc[K_ + tid] + eG[K_ + tid];
            const float mean = gsum * (1.f / D_);
            const float var  = gsq * (1.f / D_) - mean * mean;
            sMean[tid] = mean;
            sRstd[tid] = rsqrtf(var + EPSLN);
        }
        __syncthreads();   // sMean/sRstd visible to B's M update
        float uu = 0.f;
        if (isA) {
            if (hb == 0) {
                const float fsum = sF[0] + eF[0], fsq = sF[1] + eF[1];
                const float fmn = fsum * (1.f / D_);
                const float fvr = fsq * (1.f / D_) - fmn * fmn;
                const float frs = rsqrtf(fvr + EPSLN);
                const float outt = (hf - fmn) * frs * cA3 + cA4;
                uu = outt + scat[og];
                float b0 = uu, b1 = uu * uu;
                #pragma unroll
                for (int off = 1; off < 32; off <<= 1) {
                    b0 += __shfl_xor_sync(0xffffffffu, b0, off);
                    b1 += __shfl_xor_sync(0xffffffffu, b1, off);
                }
                if (lane == 0) { sUW[wid][0] = b0; sUW[wid][1] = b1; }
            }
            barA();
            if (tid < 2) {
                const float s = sUW[0][tid] + sUW[1][tid] + sUW[2][tid] + sUW[3][tid];
                sU[tid] = s;
                st_peer_f32(peer_addr(smem_u32(&eU[tid]), peer), s);
            }
        } else {
            // M update: 2 threads per row, 8 cols each (local + peer mirror)
            const int colb = (gt & 1) * 8;
            float nm[8];
            #pragma unroll
            for (int c = 0; c < 8; ++c) {
                const int j = colb + c;
                const float al = gw * sEvict[j];
                const float wr = (sG[urow][j] - sMean[j]) * sRstd[j] * cgU + cbU;
                nm[c] = sM[grow][j] * (1.f - al * sE[urow][j]) + al * wr;
            }
            float4* rowp = reinterpret_cast<float4*>(&sM[grow][colb]);
            rowp[0] = make_float4(nm[0], nm[1], nm[2], nm[3]);
            rowp[1] = make_float4(nm[4], nm[5], nm[6], nm[7]);
            uint32_t ra = peer_addr(smem_u32(&sM[grow][colb]), peer);
            st_peer_f128(ra,      make_float4(nm[0], nm[1], nm[2], nm[3]));
            st_peer_f128(ra + 16, make_float4(nm[4], nm[5], nm[6], nm[7]));
        }
        cluster_sync_();   // B4: out-LN partials + peer M halves visible

        if (isA && hb == 0) {
            const float usum = sU[0] + eU[0], usq = sU[1] + eU[1];
            const float um = usum * (1.f / D_);
            const float uv = usq * (1.f / D_) - um * um;
            const float rr = rsqrtf(uv + EPSLN);
            out[((size_t)t * B_ + b) * D_ + og] = (uu - um) * rr * ongo + onbo;
        }
    }

    // proto = transpose(M, (1,0,2)) : [K, B, d]
    if (isA && hb == 0) {
        #pragma unroll
        for (int j = 0; j < K_; ++j)
            out[(size_t)S_ * B_ * D_ + ((size_t)j * B_ + b) * D_ + og] = sM[og][j];
    }
}

extern "C" void kernel_launch(void* const* d_in, const int* in_sizes, int n_in,
                              void* d_out, int out_size) {
    (void)in_sizes; (void)n_in; (void)out_size;
    memunit_kernel<<<2 * B_, NT>>>(
        (const float*)d_in[0],  (const float*)d_in[1],
        (const float*)d_in[2],  (const float*)d_in[3],
        (const float*)d_in[4],  (const float*)d_in[5],
        (const float*)d_in[6],  (const float*)d_in[7],
        (const float*)d_in[8],  (const float*)d_in[9],
        (const float*)d_in[10], (const float*)d_in[11],
        (const float*)d_in[12], (const float*)d_in[13],
        (const float*)d_in[14], (const float*)d_in[15],
        (const float*)d_in[16], (const float*)d_in[17],
        (const float*)d_in[18], (const float*)d_in[19],
        (const float*)d_in[20], (const float*)d_in[21],
        (const float*)d_in[22], (const float*)d_in[23],
        (float*)d_out);
}

// round 13
// speedup vs baseline: 1.0702x; 1.0702x over previous
#include <cuda_runtime.h>
#include <math.h>
#include <stdint.h>

// MemoryUnit, Round 12: 2-CTA cluster per batch element, 512 threads/CTA.
// vs R10/R11: q, Kvec, logits, softmax, mbar, r are computed FULLY and
// redundantly in both CTAs (cheap: ~780 FFMA/thread) -> the B0/B1/B2 cluster
// syncs are eliminated. Only 2 cluster syncs/step remain:
//   C1: gstat + fu-LN + wg2 o-sums   C2: out-LN sums + M-mirror visibility.
// Group B's eg/wc GEMM runs uninterrupted (full-depth, software-pipelineable).

namespace {
constexpr int S_ = 2048;
constexpr int B_ = 64;
constexpr int D_ = 256;
constexpr int K_ = 16;
constexpr int NT = 512;
constexpr float EPSLN = 1e-5f;
constexpr float MOMC  = 0.9f;

__device__ __forceinline__ float geluf(float v) {
    return 0.5f * v * (1.0f + erff(v * 0.70710678118654752440f));
}
__device__ __forceinline__ float sigmf(float v) {
    return 1.0f / (1.0f + expf(-v));
}
__device__ __forceinline__ uint32_t smem_u32(const void* p) {
    return (uint32_t)__cvta_generic_to_shared(const_cast<void*>(p));
}
__device__ __forceinline__ uint32_t peer_addr(uint32_t la, uint32_t peer) {
    uint32_t ra;
    asm("mapa.shared::cluster.u32 %0, %1, %2;" : "=r"(ra) : "r"(la), "r"(peer));
    return ra;
}
__device__ __forceinline__ void st_peer_f32(uint32_t ra, float v) {
    asm volatile("st.shared::cluster.f32 [%0], %1;" :: "r"(ra), "f"(v) : "memory");
}
__device__ __forceinline__ void st_peer_f128(uint32_t ra, float4 v) {
    asm volatile("st.shared::cluster.v4.f32 [%0], {%1,%2,%3,%4};"
                 :: "r"(ra), "f"(v.x), "f"(v.y), "f"(v.z), "f"(v.w) : "memory");
}
__device__ __forceinline__ void cluster_sync_() {
    asm volatile("barrier.cluster.arrive.aligned;\n\t"
                 "barrier.cluster.wait.aligned;" ::: "memory");
}
__device__ __forceinline__ void barA() { asm volatile("bar.sync 1, 256;" ::: "memory"); }
} // namespace

__global__ __launch_bounds__(NT, 1) __cluster_dims__(2, 1, 1)
void memunit_kernel(
    const float* __restrict__ x,     const float* __restrict__ slot_init,
    const float* __restrict__ Wq,    const float* __restrict__ bq,
    const float* __restrict__ Wk,    const float* __restrict__ bk,
    const float* __restrict__ Wv,    const float* __restrict__ bv,
    const float* __restrict__ wg1W,  const float* __restrict__ wg1b,
    const float* __restrict__ wg2W,  const float* __restrict__ wg2b,
    const float* __restrict__ egW,   const float* __restrict__ egb,
    const float* __restrict__ wcW,   const float* __restrict__ wcb,
    const float* __restrict__ wclng, const float* __restrict__ wclnb,
    const float* __restrict__ fuW,   const float* __restrict__ fub,
    const float* __restrict__ fulng, const float* __restrict__ fulnb,
    const float* __restrict__ ong,   const float* __restrict__ onb,
    float* __restrict__ out)
{
    __shared__ float sM[D_][K_];       // full M, feature-major, peer-mirrored
    __shared__ float scat[2 * D_];     // [x_t | r], fully local now
    __shared__ float sQ[D_];           // full q (with bias), local
    __shared__ float sKv[D_];          // Wk @ q, all 256 rows, local
    __shared__ float sMbar[D_];        // attn-weighted slot average, local
    __shared__ float sG[128][K_];      // gelu(write pre-act), local-o rows
    __shared__ float sE[128][K_];      // sigmoid(erase pre-act)
    __shared__ float sLP[8][K_];       // logit warp partials (8 A warps)
    __shared__ float sGP[4][2 * K_];   // wc-warp gstat partials
    __shared__ float sGloc[2 * K_], eG[2 * K_];
    __shared__ float sFBf[128], sFBg[128]; // B's fu-hi / wg1-hi partials per o
    __shared__ float sBRf[4][2];       // fu-LN warp partials (A warps 0-3)
    __shared__ float sBRg[4];          // wg2 warp partials (A warps 4-7)
    __shared__ float sUW[4][2];        // out-LN warp partials
    __shared__ float sF[3], eF[3], sU[2], eU[2];
    __shared__ float sAttn[K_], sEvict[K_], sPers[K_], sMean[K_], sRstd[K_];
    __shared__ float sNov;

    const int tid  = threadIdx.x;
    const int lane = tid & 31;
    const int wid  = tid >> 5;
    const bool isA = tid < 256;
    const int gt   = tid & 255;        // group-local id
    const int o    = gt & 127;         // half-width output feature
    const int hb   = gt >> 7;          // role: A: fu/wg1 select; B: eg/wc select
    uint32_t rank;
    asm("mov.u32 %0, %%cluster_ctarank;" : "=r"(rank));
    const uint32_t peer = rank ^ 1u;
    const int b  = blockIdx.x >> 1;
    const int og = (int)rank * 128 + o;   // this CTA's output column

    if (tid < D_) {
        #pragma unroll
        for (int j = 0; j < K_; ++j) sM[tid][j] = slot_init[j * D_ + tid];
    }
    if (tid < K_) sPers[tid] = 0.f;

    const float wg2b0 = wg2b[0];
    // A full-width constants (o = gt, 0..255)
    float bqF = 0.f, bvF = 0.f;
    // A half-width constants
    float cA2 = 0.f, cA3 = 0.f, cA4 = 0.f, ongo = 0.f, onbo = 0.f;
    if (isA) {
        bqF = bq[gt]; bvF = bv[gt];
        if (hb == 0) {
            cA2 = fub[og]; cA3 = fulng[og]; cA4 = fulnb[og];
            ongo = ong[og]; onbo = onb[og];
        } else {
            cA2 = wg1b[og]; cA3 = wg2W[og];
        }
    }
    const float cbM = hb ? wcb[og] : egb[og];   // B epilogue bias
    const int  urow = gt >> 1;                  // B M-update row (local)
    const int  grow = (int)rank * 128 + urow;
    float cgU = 0.f, cbU = 0.f;
    if (!isA) { cgU = wclng[grow]; cbU = wclnb[grow]; }
    const float* Wm = hb ? wcW : egW;           // B GEMM matrix
    const float* Wf = hb ? wg1W : fuW;          // fu/wg1 matrix per role
    __syncthreads();

    for (int t = 0; t < S_; ++t) {
        if (tid < D_) scat[tid] = x[((size_t)t * B_ + b) * D_ + tid];
        __syncthreads();   // S0

        if (isA) {
            // ---- q = x @ Wq + bq: FULL width, thread per o = gt ----
            float q = 0.f;
            for (int c = 0; c < D_; c += 8) {
                float w[8];
                #pragma unroll
                for (int u = 0; u < 8; ++u) w[u] = Wq[(c + u) * D_ + gt];
                #pragma unroll
                for (int u = 0; u < 8; ++u) q = fmaf(scat[c + u], w[u], q);
            }
            sQ[gt] = q + bqF;
            barA();
            // ---- Kvec: all 256 rows, 8 A warps, warp-per-row ----
            const float4 q4lo = reinterpret_cast<const float4*>(sQ)[lane];
            const float4 q4hi = reinterpret_cast<const float4*>(sQ)[lane + 32];
            for (int r = wid; r < D_; r += 8) {
                const float* wr = Wk + (size_t)r * D_;
                const float4 wlo = reinterpret_cast<const float4*>(wr)[lane];
                const float4 whi = reinterpret_cast<const float4*>(wr)[lane + 32];
                float a = wlo.x * q4lo.x;
                a = fmaf(wlo.y, q4lo.y, a);
                a = fmaf(wlo.z, q4lo.z, a);
                a = fmaf(wlo.w, q4lo.w, a);
                a = fmaf(whi.x, q4hi.x, a);
                a = fmaf(whi.y, q4hi.y, a);
                a = fmaf(whi.z, q4hi.z, a);
                a = fmaf(whi.w, q4hi.w, a);
                #pragma unroll
                for (int off = 16; off; off >>= 1)
                    a += __shfl_xor_sync(0xffffffffu, a, off);
                if (lane == 0) sKv[r] = a;
            }
            barA();
            // ---- logit partials: thread = i-row (all 256 rows) ----
            {
                const float kv = sKv[gt];
                const float4* mr = reinterpret_cast<const float4*>(sM[gt]);
                const float4 m0 = mr[0], m1 = mr[1], m2 = mr[2], m3 = mr[3];
                const float mv[K_] = {m0.x,m0.y,m0.z,m0.w, m1.x,m1.y,m1.z,m1.w,
                                      m2.x,m2.y,m2.z,m2.w, m3.x,m3.y,m3.z,m3.w};
                float p[K_];
                #pragma unroll
                for (int j = 0; j < K_; ++j) p[j] = mv[j] * kv;
                #pragma unroll
                for (int off = 1; off < 32; off <<= 1) {
                    #pragma unroll
                    for (int j = 0; j < K_; ++j)
                        p[j] += __shfl_xor_sync(0xffffffffu, p[j], off);
                }
                if (lane == 0) {
                    #pragma unroll
                    for (int j = 0; j < K_; ++j) sLP[wid][j] = p[j];
                }
            }
            barA();
            // ---- softmax / pers / evict: fully local (identical in both CTAs) ----
            if (tid < K_) {
                float l = 0.f;
                #pragma unroll
                for (int w = 0; w < 8; ++w) l += sLP[w][tid];
                l *= 0.0625f;
                float mx = l;
                #pragma unroll
                for (int off = 8; off; off >>= 1) mx = fmaxf(mx, __shfl_xor_sync(0xffffu, mx, off, 16));
                const float e = expf(l - mx);
                float s = e;
                #pragma unroll
                for (int off = 8; off; off >>= 1) s += __shfl_xor_sync(0xffffu, s, off, 16);
                const float a = e / s;
                sAttn[tid] = a;
                if (tid == 0) sNov = 1.f - 1.f / s;
                const float pr = MOMC * sPers[tid] + (1.f - MOMC) * a;
                sPers[tid] = pr;
                float el = -4.f * pr, em = el;
                #pragma unroll
                for (int off = 8; off; off >>= 1) em = fmaxf(em, __shfl_xor_sync(0xffffu, em, off, 16));
                const float ee = expf(el - em);
                float es = ee;
                #pragma unroll
                for (int off = 8; off; off >>= 1) es += __shfl_xor_sync(0xffffu, es, off, 16);
                sEvict[tid] = ee / es;
            }
            barA();
            // ---- m-bar: thread per feature (full width) ----
            {
                const float4* mr = reinterpret_cast<const float4*>(sM[gt]);
                const float4 m0 = mr[0], m1 = mr[1], m2 = mr[2], m3 = mr[3];
                const float mv[K_] = {m0.x,m0.y,m0.z,m0.w, m1.x,m1.y,m1.z,m1.w,
                                      m2.x,m2.y,m2.z,m2.w, m3.x,m3.y,m3.z,m3.w};
                float a = 0.f;
                #pragma unroll
                for (int j = 0; j < K_; ++j) a = fmaf(sAttn[j], mv[j], a);
                sMbar[gt] = a;
            }
            barA();
            // ---- r = m-bar @ Wv + bv: FULL width, thread per o = gt ----
            float r = 0.f;
            for (int c = 0; c < D_; c += 8) {
                float w[8];
                #pragma unroll
                for (int u = 0; u < 8; ++u) w[u] = Wv[(c + u) * D_ + gt];
                #pragma unroll
                for (int u = 0; u < 8; ++u) r = fmaf(sMbar[c + u], w[u], r);
            }
            scat[D_ + gt] = r + bvF;
        } else {
            // ================= GROUP B: uninterrupted eg/wc GEMM =================
            float acc[K_];
            float aux = 0.f;
            #pragma unroll
            for (int j = 0; j < K_; ++j) acc[j] = 0.f;
            for (int c = 0; c < D_; c += 4) {
                float wa[4], ws[4];
                #pragma unroll
                for (int u = 0; u < 4; ++u) {
                    wa[u] = Wm[(c + u) * D_ + og];          // x-part row
                    ws[u] = Wm[(D_ + c + u) * D_ + og];     // slot-part row
                }
                #pragma unroll
                for (int u = 0; u < 4; ++u) {
                    const int i = c + u;
                    aux = fmaf(scat[i], wa[u], aux);
                    const float4* mr = reinterpret_cast<const float4*>(sM[i]);
                    const float4 m0 = mr[0], m1 = mr[1], m2 = mr[2], m3 = mr[3];
                    const float mv[K_] = {m0.x,m0.y,m0.z,m0.w, m1.x,m1.y,m1.z,m1.w,
                                          m2.x,m2.y,m2.z,m2.w, m3.x,m3.y,m3.z,m3.w};
                    #pragma unroll
                    for (int j = 0; j < K_; ++j)
                        acc[j] = fmaf(mv[j], ws[u], acc[j]);
                }
            }
            if (hb == 0) {   // erase epilogue (warps 8-11)
                float e[K_];
                #pragma unroll
                for (int j = 0; j < K_; ++j) e[j] = sigmf(acc[j] + aux + cbM);
                float4* er = reinterpret_cast<float4*>(sE[o]);
                er[0] = make_float4(e[0],  e[1],  e[2],  e[3]);
                er[1] = make_float4(e[4],  e[5],  e[6],  e[7]);
                er[2] = make_float4(e[8],  e[9],  e[10], e[11]);
                er[3] = make_float4(e[12], e[13], e[14], e[15]);
            } else {         // write-candidate epilogue + gstats (warps 12-15)
                float g[K_], gs[K_], gq[K_];
                #pragma unroll
                for (int j = 0; j < K_; ++j) {
                    g[j]  = geluf(acc[j] + aux + cbM);
                    gs[j] = g[j];
                    gq[j] = g[j] * g[j];
                }
                #pragma unroll
                for (int off = 1; off < 32; off <<= 1) {
                    #pragma unroll
                    for (int j = 0; j < K_; ++j) {
                        gs[j] += __shfl_xor_sync(0xffffffffu, gs[j], off);
                        gq[j] += __shfl_xor_sync(0xffffffffu, gq[j], off);
                    }
                }
                if (lane == 0) {
                    #pragma unroll
                    for (int j = 0; j < K_; ++j) {
                        sGP[wid - 12][j]      = gs[j];
                        sGP[wid - 12][K_ + j] = gq[j];
                    }
                }
                float4* gr = reinterpret_cast<float4*>(sG[o]);
                gr[0] = make_float4(g[0],  g[1],  g[2],  g[3]);
                gr[1] = make_float4(g[4],  g[5],  g[6],  g[7]);
                gr[2] = make_float4(g[8],  g[9],  g[10], g[11]);
                gr[3] = make_float4(g[12], g[13], g[14], g[15]);
            }
        }
        __syncthreads();   // S1: r + sG/sE/sGP ready; A done reading sM

        // ---- fu / wg1 quadrants: A = cat[0..255], B = cat[256..511] ----
        float accf = 0.f;
        {
            const int base = isA ? 0 : 256;
            for (int c = 0; c < 256; c += 8) {
                float w[8];
                #pragma unroll
                for (int u = 0; u < 8; ++u) w[u] = Wf[(base + c + u) * D_ + og];
                #pragma unroll
                for (int u = 0; u < 8; ++u) accf = fmaf(scat[base + c + u], w[u], accf);
            }
        }
        if (!isA) { if (hb == 0) sFBf[o] = accf; else sFBg[o] = accf; }
        __syncthreads();   // S2

        float hf = 0.f;
        if (isA) {
            if (hb == 0) {
                hf = geluf(accf + sFBf[o] + cA2);
                float b0 = hf, b1 = hf * hf;
                #pragma unroll
                for (int off = 1; off < 32; off <<= 1) {
                    b0 += __shfl_xor_sync(0xffffffffu, b0, off);
                    b1 += __shfl_xor_sync(0xffffffffu, b1, off);
                }
                if (lane == 0) { sBRf[wid][0] = b0; sBRf[wid][1] = b1; }
            } else {
                const float hg = geluf(accf + sFBg[o] + cA2);
                float a2 = hg * cA3;
                #pragma unroll
                for (int off = 1; off < 32; off <<= 1)
                    a2 += __shfl_xor_sync(0xffffffffu, a2, off);
                if (lane == 0) sBRg[wid - 4] = a2;
            }
            barA();
            if (tid < 3) {
                float s;
                if (tid < 2) s = sBRf[0][tid] + sBRf[1][tid] + sBRf[2][tid] + sBRf[3][tid];
                else         s = sBRg[0] + sBRg[1] + sBRg[2] + sBRg[3];
                sF[tid] = s;
                st_peer_f32(peer_addr(smem_u32(&eF[tid]), peer), s);
            }
        } else if (gt < 2 * K_) {
            // gstat combine + exchange (sGP ready since S1)
            const float s = sGP[0][gt] + sGP[1][gt] + sGP[2][gt] + sGP[3][gt];
            sGloc[gt] = s;
            st_peer_f32(peer_addr(smem_u32(&eG[gt]), peer), s);
        }
        cluster_sync_();   // C1: eF + eG exchanged

        const float gw = sigmf(sF[2] + eF[2] + wg2b0) * sNov;
        if (tid < K_) {
            sPers[tid] += sEvict[tid] * gw * 0.1f;
            const float gsum = sGloc[tid] + eG[tid];
            const float gsq  = sGloc[K_ + tid] + eG[K_ + tid];
            const float mean = gsum * (1.f / D_);
            const float var  = gsq * (1.f / D_) - mean * mean;
            sMean[tid] = mean;
            sRstd[tid] = rsqrtf(var + EPSLN);
        }
        __syncthreads();   // S3: mean/rstd visible

        float uu = 0.f;
        if (isA) {
            if (hb == 0) {
                const float fsum = sF[0] + eF[0], fsq = sF[1] + eF[1];
                const float fmn = fsum * (1.f / D_);
                const float fvr = fsq * (1.f / D_) - fmn * fmn;
                const float frs = rsqrtf(fvr + EPSLN);
                const float outt = (hf - fmn) * frs * cA3 + cA4;
                uu = outt + scat[og];
                float b0 = uu, b1 = uu * uu;
                #pragma unroll
                for (int off = 1; off < 32; off <<= 1) {
                    b0 += __shfl_xor_sync(0xffffffffu, b0, off);
                    b1 += __shfl_xor_sync(0xffffffffu, b1, off);
                }
                if (lane == 0) { sUW[wid][0] = b0; sUW[wid][1] = b1; }
            }
            barA();
            if (tid < 2) {
                const float s = sUW[0][tid] + sUW[1][tid] + sUW[2][tid] + sUW[3][tid];
                sU[tid] = s;
                st_peer_f32(peer_addr(smem_u32(&eU[tid]), peer), s);
            }
        } else {
            // M update: 2 threads per row, 8 cols each (local + peer mirror)
            const int colb = (gt & 1) * 8;
            float nm[8];
            #pragma unroll
            for (int c = 0; c < 8; ++c) {
                const int j = colb + c;
                const float al = gw * sEvict[j];
                const float wr = (sG[urow][j] - sMean[j]) * sRstd[j] * cgU + cbU;
                nm[c] = sM[grow][j] * (1.f - al * sE[urow][j]) + al * wr;
            }
            float4* rowp = reinterpret_cast<float4*>(&sM[grow][colb]);
            rowp[0] = make_float4(nm[0], nm[1], nm[2], nm[3]);
            rowp[1] = make_float4(nm[4], nm[5], nm[6], nm[7]);
            uint32_t ra = peer_addr(smem_u32(&sM[grow][colb]), peer);
            st_peer_f128(ra,      make_float4(nm[0], nm[1], nm[2], nm[3]));
            st_peer_f128(ra + 16, make_float4(nm[4], nm[5], nm[6], nm[7]));
        }
        cluster_sync_();   // C2: eU + peer M halves visible

        if (isA && hb == 0) {
            const float usum = sU[0] + eU[0], usq = sU[1] + eU[1];
            const float um = usum * (1.f / D_);
            const float uv = usq * (1.f / D_) - um * um;
            const float rr = rsqrtf(uv + EPSLN);
            out[((size_t)t * B_ + b) * D_ + og] = (uu - um) * rr * ongo + onbo;
        }
    }

    // proto = transpose(M, (1,0,2)) : [K, B, d]
    if (isA && hb == 0) {
        #pragma unroll
        for (int j = 0; j < K_; ++j)
            out[(size_t)S_ * B_ * D_ + ((size_t)j * B_ + b) * D_ + og] = sM[og][j];
    }
}

extern "C" void kernel_launch(void* const* d_in, const int* in_sizes, int n_in,
                              void* d_out, int out_size) {
    (void)in_sizes; (void)n_in; (void)out_size;
    memunit_kernel<<<2 * B_, NT>>>(
        (const float*)d_in[0],  (const float*)d_in[1],
        (const float*)d_in[2],  (const float*)d_in[3],
        (const float*)d_in[4],  (const float*)d_in[5],
        (const float*)d_in[6],  (const float*)d_in[7],
        (const float*)d_in[8],  (const float*)d_in[9],
        (const float*)d_in[10], (const float*)d_in[11],
        (const float*)d_in[12], (const float*)d_in[13],
        (const float*)d_in[14], (const float*)d_in[15],
        (const float*)d_in[16], (const float*)d_in[17],
        (const float*)d_in[18], (const float*)d_in[19],
        (const float*)d_in[20], (const float*)d_in[21],
        (const float*)d_in[22], (const float*)d_in[23],
        (float*)d_out);
}